// round 6
// baseline (speedup 1.0000x reference)
#include <cuda_runtime.h>
#include <cstdint>

#define BATCH 512
#define TLEN  512
#define S     64
#define NEG_INF -10000.0f
#define NTHR  256      // tid = 4*n + h ; n = next tag, h = prev quarter
#define RD    8        // backtrace ring depth (prefetch distance 7)

typedef unsigned long long ull;

// vmax history: [b][t-1][n], pre-feat step maxima. 512*511*64*4 = 66.98 MB.
__device__ __align__(16) float g_vmax[(size_t)BATCH * (TLEN - 1) * S];

__device__ __forceinline__ ull ADD2(ull a, ull b) {
    ull r; asm("add.rn.f32x2 %0, %1, %2;" : "=l"(r) : "l"(a), "l"(b)); return r;
}
// Unpack is register-pair aliasing: compiles to zero instructions.
__device__ __forceinline__ void UNPK(ull v, float& lo, float& hi) {
    unsigned int l, h;
    asm("mov.b64 {%0,%1}, %2;" : "=r"(l), "=r"(h) : "l"(v));
    lo = __uint_as_float(l); hi = __uint_as_float(h);
}

__global__ __launch_bounds__(NTHR) void viterbi_all(
    const float* __restrict__ logits,       // (B, T, S)
    const float* __restrict__ masks,        // (B, T)
    const float* __restrict__ transitions,  // (S, S) [next, prev]
    float* __restrict__ out)                // [0,B): path_score ; [B,...): best_seq
{
    const int b    = blockIdx.x;
    const int tid  = threadIdx.x;
    const int n    = tid >> 2;    // next tag 0..63
    const int h    = tid & 3;     // prev quarter 0..3
    const int lane = tid & 31;
    const int warp = tid >> 5;

    __shared__ __align__(16) float fvbuf[2][S];
    __shared__ __align__(16) float smask[TLEN];
    __shared__ __align__(16) float tr_s[S * S];     // full transitions (16 KB)
    __shared__ __align__(16) float ring_vm[RD][S];  // vmax rows (eq targets)
    __shared__ __align__(16) float ring_fv[RD][S];  // fv rows
    __shared__ unsigned char seq_s[TLEN];

    // ---- stage transitions (16 KB) + mask row (2 KB) ----
    {
        const float4* ts = (const float4*)transitions;
        float4* td = (float4*)tr_s;
        for (int i = tid; i < S * S / 4; i += NTHR) td[i] = ts[i];
        if (tid < TLEN / 4) {
            const float4* ms = (const float4*)(masks + (size_t)b * TLEN);
            ((float4*)smask)[tid] = ms[tid];
        }
        if (h == 0) fvbuf[0][n] = (n == 0) ? 0.0f : NEG_INF;
    }
    __syncthreads();

    // ---- my 16 transitions as 8 packed f32x2 (from shared) ----
    ull tr2[8];
    {
        const ulonglong2* tp = (const ulonglong2*)(tr_s + n * S + h * 16);
#pragma unroll
        for (int i = 0; i < 4; i++) {
            ulonglong2 v = tp[i];
            tr2[2 * i] = v.x; tr2[2 * i + 1] = v.y;
        }
    }

    const float* lg = logits + (size_t)b * TLEN * S;
    float* vmb = g_vmax + (size_t)b * (TLEN - 1) * S;

    // ---- emission prefetch pipeline (h==0 threads only) ----
    float fb[4];
    if (h == 0) {
#pragma unroll
        for (int i = 0; i < 4; i++) fb[i] = lg[(1 + i) * S + n];
    }

    // =================== forward: max-only recursion ===================
#pragma unroll 4
    for (int t = 1; t < TLEN; t++) {
        float feat = 0.0f, m = 0.0f;
        if (h == 0) {
            feat = fb[0];
            fb[0] = fb[1]; fb[1] = fb[2]; fb[2] = fb[3];
            int tp = t + 4; if (tp > TLEN - 1) tp = TLEN - 1;
            fb[3] = lg[tp * S + n];
            m = smask[t];
        }

        // my 16 fv values (broadcast LDS.128 x2)
        const ulonglong2* fvp = (const ulonglong2*)(&fvbuf[(t - 1) & 1][16 * h]);
        ulonglong2 Fa = fvp[0], Fb = fvp[1];

        // 8 packed adds (fma pipe) + 15 FMNMX tree (alu pipe)
        float c[16];
        UNPK(ADD2(Fa.x, tr2[0]), c[0], c[1]);
        UNPK(ADD2(Fa.y, tr2[1]), c[2], c[3]);
        UNPK(ADD2(Fb.x, tr2[2]), c[4], c[5]);
        UNPK(ADD2(Fb.y, tr2[3]), c[6], c[7]);
        {
            const ulonglong2* fvp2 = fvp + 2;
            ulonglong2 Fc = fvp2[0], Fd = fvp2[1];
            UNPK(ADD2(Fc.x, tr2[4]), c[8],  c[9]);
            UNPK(ADD2(Fc.y, tr2[5]), c[10], c[11]);
            UNPK(ADD2(Fd.x, tr2[6]), c[12], c[13]);
            UNPK(ADD2(Fd.y, tr2[7]), c[14], c[15]);
        }
        float v01 = fmaxf(c[0], c[1]),  v23 = fmaxf(c[2], c[3]);
        float v45 = fmaxf(c[4], c[5]),  v67 = fmaxf(c[6], c[7]);
        float v89 = fmaxf(c[8], c[9]),  vab = fmaxf(c[10], c[11]);
        float vcd = fmaxf(c[12], c[13]), vef = fmaxf(c[14], c[15]);
        float v0 = fmaxf(fmaxf(v01, v23), fmaxf(v45, v67));
        float v1 = fmaxf(fmaxf(v89, vab), fmaxf(vcd, vef));
        float v = fmaxf(v0, v1);

        // merge prev quarters across lanes h=0..3
        v = fmaxf(v, __shfl_xor_sync(0xffffffffu, v, 1));
        v = fmaxf(v, __shfl_xor_sync(0xffffffffu, v, 2));

        if (h == 0) {
            vmb[(t - 1) * S + n] = v;                      // exact pre-feat max
            if (t == TLEN - 1 && n == S - 1) out[b] = v;   // path_score quirk
            fvbuf[t & 1][n] = __fadd_rn(v, __fmul_rn(feat, m));
        }
        __syncthreads();
    }

    // Hmm wait — fv[0] is only needed by pref(0); rewritten below. (fvbuf is
    // free after the forward loop; ring buffers are separate arrays.)

    // =================== backtrace: warp 0, equality search ===================
    if (warp == 0) {
        const int l = lane;

        // prefetch row i into ring slot i&(RD-1)
        auto pref = [&](int i) {
            int s = i & (RD - 1);
            float2 fv;
            if (i == 0) {
                fv.x = (2 * l == 0) ? 0.0f : NEG_INF;
                fv.y = NEG_INF;
            } else {
                float2 vp = *(const float2*)(vmb + (size_t)(i - 1) * S + 2 * l);
                float2 ft = *(const float2*)(lg + (size_t)i * S + 2 * l);
                float m = smask[i];
                fv.x = __fadd_rn(vp.x, __fmul_rn(ft.x, m));
                fv.y = __fadd_rn(vp.y, __fmul_rn(ft.y, m));
            }
            *(float2*)&ring_fv[s][2 * l] = fv;
            float2 vm = *(const float2*)(vmb + (size_t)i * S + 2 * l);
            *(float2*)&ring_vm[s][2 * l] = vm;
        };

        for (int j = 0; j < RD - 1; j++) {
            int i = (TLEN - 2) - j;
            if (i >= 0) pref(i);
        }
        __syncwarp();

        float2 fv_cur = *(const float2*)&ring_fv[(TLEN - 2) & (RD - 1)][2 * l];

        // lowest p with fv_cur[p] + tr[tag][p] == vmax_hist[i][tag]
        auto eq_step = [&](int i, int tag) -> int {
            float tgt = ring_vm[i & (RD - 1)][tag];
            float2 trp = *(const float2*)(tr_s + tag * S + 2 * l);
            float c0 = __fadd_rn(fv_cur.x, trp.x);
            float c1 = __fadd_rn(fv_cur.y, trp.y);
            unsigned m0 = __ballot_sync(0xffffffffu, c0 == tgt);
            unsigned m1 = __ballot_sync(0xffffffffu, c1 == tgt);
            int p0 = m0 ? ((__ffs(m0) - 1) << 1) : 1000;
            int p1 = m1 ? (((__ffs(m1) - 1) << 1) + 1) : 1000;
            int p = p0 < p1 ? p0 : p1;
            return p & 63;
        };

        // torch quirk: seed from bp(T-2, S-1); last table applied twice
        int tag = eq_step(TLEN - 2, S - 1);
        for (int i = TLEN - 2; i >= 0; i--) {
            if (l == 0) seq_s[i] = (unsigned char)tag;
            int nt = eq_step(i, tag);
            int ip = i - (RD - 1);
            if (ip >= 0) pref(ip);
            __syncwarp();
            if (i > 0)
                fv_cur = *(const float2*)&ring_fv[(i - 1) & (RD - 1)][2 * l];
            tag = nt;
        }
    }
    __syncthreads();

    // ---- coalesced output of the sequence ----
    float* o = out + BATCH + (size_t)b * (TLEN - 1);
    for (int i = tid; i < TLEN - 1; i += NTHR) o[i] = (float)seq_s[i];
}

extern "C" void kernel_launch(void* const* d_in, const int* in_sizes, int n_in,
                              void* d_out, int out_size)
{
    const float* logits      = (const float*)d_in[0];
    const float* masks       = (const float*)d_in[1];
    const float* transitions = (const float*)d_in[2];
    float* out = (float*)d_out;

    viterbi_all<<<BATCH, NTHR>>>(logits, masks, transitions, out);
}

// round 7
// speedup vs baseline: 1.3950x; 1.3950x over previous
#include <cuda_runtime.h>
#include <cstdint>

#define BATCH 512
#define TLEN  512
#define S     64
#define NEG_INF -10000.0f
#define NTHR  128
#define BPB   2      // batches per block
#define RD    8      // backtrace ring depth

typedef unsigned long long ull;

// vmax history: [b][t-1][n], pre-feat step maxima. 512*511*64*4 = 66.98 MB.
__device__ __align__(16) float g_vmax[(size_t)BATCH * (TLEN - 1) * S];

__device__ __forceinline__ ull ADD2(ull a, ull b) {
    ull r; asm("add.rn.f32x2 %0, %1, %2;" : "=l"(r) : "l"(a), "l"(b)); return r;
}
// max of the two packed halves; the mov.b64 pair-split is register aliasing.
__device__ __forceinline__ float PMAX(ull v) {
    unsigned int l, h;
    asm("mov.b64 {%0,%1}, %2;" : "=r"(l), "=r"(h) : "l"(v));
    return fmaxf(__uint_as_float(l), __uint_as_float(h));
}

__global__ __launch_bounds__(NTHR) void viterbi_all(
    const float* __restrict__ logits,       // (B, T, S)
    const float* __restrict__ masks,        // (B, T)
    const float* __restrict__ transitions,  // (S, S) [next, prev]
    float* __restrict__ out)                // [0,B): path_score ; [B,...): best_seq
{
    const int tid  = threadIdx.x;
    const int lane = tid & 31;
    const int w    = tid >> 5;
    const int s    = w >> 1;                   // batch slot 0/1
    const int n    = ((w & 1) << 5) | lane;    // my next-tag 0..63
    const int b    = blockIdx.x * BPB + s;

    __shared__ __align__(16) float tr_s[S * S];          // 16 KB, shared by slots
    __shared__ __align__(16) float fvbuf[BPB][2][S];
    __shared__ __align__(16) float smask[BPB][TLEN];
    __shared__ __align__(16) float ring_vm[BPB][RD][S];
    __shared__ __align__(16) float ring_fv[BPB][RD][S];
    __shared__ unsigned char seq_s[BPB][TLEN];

    // ---- stage transitions (16 KB) + my batch's mask row ----
    {
        const float4* ts = (const float4*)transitions;
        float4* td = (float4*)tr_s;
        for (int i = tid; i < S * S / 4; i += NTHR) td[i] = ts[i];
        const float4* ms = (const float4*)(masks + (size_t)b * TLEN);
        float4* md = (float4*)smask[s];
        const int q = tid & 63;                 // 64 threads per slot
        md[q] = ms[q];
        md[q + 64] = ms[q + 64];
        fvbuf[s][0][n] = (n == 0) ? 0.0f : NEG_INF;
    }
    __syncthreads();

    // ---- my full transitions row (64 floats) as 32 packed f32x2 regs ----
    ull tr2[32];
    {
        const ulonglong2* tp = (const ulonglong2*)(tr_s + n * S);
#pragma unroll
        for (int i = 0; i < 16; i++) {
            ulonglong2 v = tp[i];
            tr2[2 * i] = v.x; tr2[2 * i + 1] = v.y;
        }
    }

    const float* lg = logits + (size_t)b * TLEN * S;
    float* vmb = g_vmax + (size_t)b * (TLEN - 1) * S;

    // ---- emission prefetch pipeline (depth 4), coalesced per warp ----
    float fb[4];
#pragma unroll
    for (int i = 0; i < 4; i++) fb[i] = lg[(1 + i) * S + n];

    // =================== forward: max-only recursion, no shfl ===================
    for (int t = 1; t < TLEN; t++) {
        float feat = fb[0];
        fb[0] = fb[1]; fb[1] = fb[2]; fb[2] = fb[3];
        int tpi = t + 4; if (tpi > TLEN - 1) tpi = TLEN - 1;
        fb[3] = lg[tpi * S + n];

        float m = smask[s][t];

        const ulonglong2* fvp = (const ulonglong2*)fvbuf[s][(t - 1) & 1];

        // 4 independent groups of 16 prevs: 8 ADD2 + 8 pair-max + 7-deep merge
        float acc[4];
#pragma unroll
        for (int j = 0; j < 4; j++) {
            ulonglong2 F0 = fvp[4 * j + 0];
            ulonglong2 F1 = fvp[4 * j + 1];
            ulonglong2 F2 = fvp[4 * j + 2];
            ulonglong2 F3 = fvp[4 * j + 3];
            float m0 = PMAX(ADD2(F0.x, tr2[8 * j + 0]));
            float m1 = PMAX(ADD2(F0.y, tr2[8 * j + 1]));
            float m2 = PMAX(ADD2(F1.x, tr2[8 * j + 2]));
            float m3 = PMAX(ADD2(F1.y, tr2[8 * j + 3]));
            float m4 = PMAX(ADD2(F2.x, tr2[8 * j + 4]));
            float m5 = PMAX(ADD2(F2.y, tr2[8 * j + 5]));
            float m6 = PMAX(ADD2(F3.x, tr2[8 * j + 6]));
            float m7 = PMAX(ADD2(F3.y, tr2[8 * j + 7]));
            acc[j] = fmaxf(fmaxf(fmaxf(m0, m1), fmaxf(m2, m3)),
                           fmaxf(fmaxf(m4, m5), fmaxf(m6, m7)));
        }
        float v = fmaxf(fmaxf(acc[0], acc[1]), fmaxf(acc[2], acc[3]));

        vmb[(t - 1) * S + n] = v;                      // exact pre-feat step max
        if (t == TLEN - 1 && n == S - 1) out[b] = v;   // path_score quirk
        fvbuf[s][t & 1][n] = __fadd_rn(v, __fmul_rn(feat, m));
        __syncthreads();
    }

    // ========== backtrace: warp 0 -> slot 0, warp 2 -> slot 1 (parallel) ==========
    if ((w & 1) == 0) {
        const int l = lane;

        auto pref = [&](int i) {
            int sl = i & (RD - 1);
            float2 fv;
            if (i == 0) {
                fv.x = (2 * l == 0) ? 0.0f : NEG_INF;
                fv.y = NEG_INF;
            } else {
                float2 vp = *(const float2*)(vmb + (size_t)(i - 1) * S + 2 * l);
                float2 ft = *(const float2*)(lg + (size_t)i * S + 2 * l);
                float mm = smask[s][i];
                fv.x = __fadd_rn(vp.x, __fmul_rn(ft.x, mm));
                fv.y = __fadd_rn(vp.y, __fmul_rn(ft.y, mm));
            }
            *(float2*)&ring_fv[s][sl][2 * l] = fv;
            float2 vm = *(const float2*)(vmb + (size_t)i * S + 2 * l);
            *(float2*)&ring_vm[s][sl][2 * l] = vm;
        };

        for (int j = 0; j < RD - 1; j++) {
            int i = (TLEN - 2) - j;
            if (i >= 0) pref(i);
        }
        __syncwarp();

        float2 fv_cur = *(const float2*)&ring_fv[s][(TLEN - 2) & (RD - 1)][2 * l];

        // lowest p with fv_cur[p] + tr[tag][p] == vmax_hist[i][tag]
        auto eq_step = [&](int i, int tag) -> int {
            float tgt = ring_vm[s][i & (RD - 1)][tag];
            float2 trp = *(const float2*)(tr_s + tag * S + 2 * l);
            float c0 = __fadd_rn(fv_cur.x, trp.x);
            float c1 = __fadd_rn(fv_cur.y, trp.y);
            unsigned m0 = __ballot_sync(0xffffffffu, c0 == tgt);
            unsigned m1 = __ballot_sync(0xffffffffu, c1 == tgt);
            int p0 = m0 ? ((__ffs(m0) - 1) << 1) : 1000;
            int p1 = m1 ? (((__ffs(m1) - 1) << 1) + 1) : 1000;
            int p = p0 < p1 ? p0 : p1;
            return p & 63;
        };

        // torch quirk: seed from bp(T-2, S-1); last table applied twice
        int tag = eq_step(TLEN - 2, S - 1);
        for (int i = TLEN - 2; i >= 0; i--) {
            if (l == 0) seq_s[s][i] = (unsigned char)tag;
            int nt = eq_step(i, tag);
            int ip = i - (RD - 1);
            if (ip >= 0) pref(ip);
            __syncwarp();
            if (i > 0)
                fv_cur = *(const float2*)&ring_fv[s][(i - 1) & (RD - 1)][2 * l];
            tag = nt;
        }
    }
    __syncthreads();

    // ---- coalesced output of both sequences ----
#pragma unroll
    for (int ss = 0; ss < BPB; ss++) {
        float* o = out + BATCH + (size_t)(blockIdx.x * BPB + ss) * (TLEN - 1);
        for (int i = tid; i < TLEN - 1; i += NTHR) o[i] = (float)seq_s[ss][i];
    }
}

extern "C" void kernel_launch(void* const* d_in, const int* in_sizes, int n_in,
                              void* d_out, int out_size)
{
    const float* logits      = (const float*)d_in[0];
    const float* masks       = (const float*)d_in[1];
    const float* transitions = (const float*)d_in[2];
    float* out = (float*)d_out;

    viterbi_all<<<BATCH / BPB, NTHR>>>(logits, masks, transitions, out);
}